// round 1
// baseline (speedup 1.0000x reference)
#include <cuda_runtime.h>
#include <cuda_bf16.h>
#include <math.h>

// Problem constants (fixed shapes per reference)
#define BATCH    4096   // N_SEQ * N_PED
#define NSEQ     64
#define NPED     64
#define HD       64     // H_DIM
#define G2       64     // GRID*GRID
#define KDIM     4096   // G2 * HD
#define NB       1024   // BOTTLENECK
#define BN_EPS   1e-5f

// Scratch: pooled features [BATCH x KDIM] (64 MB), BN partial stats
__device__ float g_pool[(size_t)BATCH * KDIM];
__device__ float g_sum[NB];
__device__ float g_sumsq[NB];

// ---------------------------------------------------------------------------
// Kernel 1: social pooling. One block per target ped, 64 threads (one per
// h-dim). Accumulate neighbor hidden vectors into a 64-cell x 64-dim SMEM
// tile, then stream it out. SMEM fully rewritten each launch.
// ---------------------------------------------------------------------------
__global__ __launch_bounds__(64) void pool_kernel(
    const float* __restrict__ h,      // [BATCH, HD]
    const float* __restrict__ pos)    // [BATCH, 2]
{
    __shared__ float sp[G2 * HD];     // 16 KB
    __shared__ float2 spos[NPED];

    const int i     = blockIdx.x;     // global target ped
    const int scene = i / NPED;
    const int base  = scene * NPED;
    const int t     = threadIdx.x;    // 0..63

    for (int k = t; k < G2 * HD; k += 64) sp[k] = 0.0f;
    spos[t] = reinterpret_cast<const float2*>(pos)[base + t];
    __syncthreads();

    const float2 pi  = spos[i - base];
    const float  tlx = pi.x - 1.0f;
    const float  tly = pi.y + 1.0f;
    const float  brx = pi.x + 1.0f;
    const float  bry = pi.y - 1.0f;

    const int local_i = i - base;
    for (int j = 0; j < NPED; ++j) {
        if (j == local_i) continue;
        const float2 pj = spos[j];
        if (pj.x >= brx || pj.x <= tlx || pj.y >= tly || pj.y <= bry) continue;
        int cx = (int)floorf((pj.x - tlx) / 2.0f * 8.0f);
        int cy = (int)floorf((tly - pj.y) / 2.0f * 8.0f);
        int cell = cx + cy * 8;
        cell = min(max(cell, 0), G2 - 1);   // safety clamp (in-bounds guaranteed by oob test)
        sp[cell * HD + t] += h[(size_t)(base + j) * HD + t];
    }
    __syncthreads();

    float* dst = g_pool + (size_t)i * KDIM;
    for (int k = t; k < G2 * HD; k += 64) dst[k] = sp[k];
}

// ---------------------------------------------------------------------------
// Kernel 2: fp32 SIMT GEMM  X = pool @ W + b
// M=4096, K=4096, N=1024. 128x128 block tile, BK=16, 256 threads, 8x8/thread.
// ---------------------------------------------------------------------------
#define BM 128
#define BN_T 128
#define BK 16

__global__ __launch_bounds__(256) void gemm_kernel(
    const float* __restrict__ A,   // [BATCH, KDIM] = g_pool
    const float* __restrict__ B,   // [KDIM, NB]    = W
    const float* __restrict__ bias,
    float* __restrict__ X)         // [BATCH, NB]
{
    __shared__ float As[BK][BM];    // transposed A tile
    __shared__ float Bs[BK][BN_T];

    const int t  = threadIdx.x;
    const int m0 = blockIdx.y * BM;
    const int n0 = blockIdx.x * BN_T;

    const int tm0 = (t / 16) * 8;   // 0..120
    const int tn0 = (t % 16) * 8;

    // A loader coords: 2 float4 per thread
    const int a_row = t / 4;        // 0..63 (+64 second half)
    const int a_kv  = (t % 4) * 4;  // k offset 0,4,8,12
    // B loader coords: 2 float4 per thread
    const int b_row = t / 32;       // 0..7 (+8 second half)
    const int b_col = (t % 32) * 4; // 0..124

    float acc[8][8];
#pragma unroll
    for (int i = 0; i < 8; ++i)
#pragma unroll
        for (int j = 0; j < 8; ++j) acc[i][j] = 0.0f;

    for (int k0 = 0; k0 < KDIM; k0 += BK) {
        // load A tile (transposed into As[k][m])
#pragma unroll
        for (int h = 0; h < 2; ++h) {
            const int row = a_row + h * 64;
            float4 v = *reinterpret_cast<const float4*>(
                &A[(size_t)(m0 + row) * KDIM + k0 + a_kv]);
            As[a_kv + 0][row] = v.x;
            As[a_kv + 1][row] = v.y;
            As[a_kv + 2][row] = v.z;
            As[a_kv + 3][row] = v.w;
        }
        // load B tile
#pragma unroll
        for (int h = 0; h < 2; ++h) {
            const int row = b_row + h * 8;
            float4 v = *reinterpret_cast<const float4*>(
                &B[(size_t)(k0 + row) * NB + n0 + b_col]);
            *reinterpret_cast<float4*>(&Bs[row][b_col]) = v;
        }
        __syncthreads();

#pragma unroll
        for (int k = 0; k < BK; ++k) {
            float ra[8], rb[8];
#pragma unroll
            for (int i = 0; i < 8; ++i) ra[i] = As[k][tm0 + i];
#pragma unroll
            for (int j = 0; j < 8; ++j) rb[j] = Bs[k][tn0 + j];
#pragma unroll
            for (int i = 0; i < 8; ++i)
#pragma unroll
                for (int j = 0; j < 8; ++j)
                    acc[i][j] = fmaf(ra[i], rb[j], acc[i][j]);
        }
        __syncthreads();
    }

    // epilogue: add bias, store
#pragma unroll
    for (int i = 0; i < 8; ++i) {
        const int m = m0 + tm0 + i;
#pragma unroll
        for (int j = 0; j < 8; j += 4) {
            const int n = n0 + tn0 + j;
            float4 v;
            v.x = acc[i][j + 0] + bias[n + 0];
            v.y = acc[i][j + 1] + bias[n + 1];
            v.z = acc[i][j + 2] + bias[n + 2];
            v.w = acc[i][j + 3] + bias[n + 3];
            *reinterpret_cast<float4*>(&X[(size_t)m * NB + n]) = v;
        }
    }
}

// ---------------------------------------------------------------------------
// Kernel 3a: zero the stat accumulators (graph replays need fresh zeros)
// ---------------------------------------------------------------------------
__global__ void zero_stats_kernel()
{
    int t = blockIdx.x * blockDim.x + threadIdx.x;
    if (t < NB) { g_sum[t] = 0.0f; g_sumsq[t] = 0.0f; }
}

// ---------------------------------------------------------------------------
// Kernel 3b: per-column sum / sumsq. blockIdx.x = column chunk (256 cols),
// blockIdx.y = row chunk (128 rows). Adjacent threads -> adjacent columns
// -> fully coalesced reads of X.
// ---------------------------------------------------------------------------
__global__ __launch_bounds__(256) void stats_kernel(const float* __restrict__ X)
{
    const int col = blockIdx.x * 256 + threadIdx.x;
    const int r0  = blockIdx.y * 128;
    float s = 0.0f, ss = 0.0f;
    for (int r = r0; r < r0 + 128; ++r) {
        float v = X[(size_t)r * NB + col];
        s  += v;
        ss += v * v;
    }
    atomicAdd(&g_sum[col],   s);
    atomicAdd(&g_sumsq[col], ss);
}

// ---------------------------------------------------------------------------
// Kernel 4: batchnorm (population var) + ReLU, in place on d_out.
// ---------------------------------------------------------------------------
__global__ __launch_bounds__(256) void apply_kernel(
    float* __restrict__ X,
    const float* __restrict__ gamma,
    const float* __restrict__ beta)
{
    const int idx = blockIdx.x * 256 + threadIdx.x;
    const int col = idx % NB;
    const float inv_n = 1.0f / (float)BATCH;
    const float mean  = g_sum[col] * inv_n;
    const float var   = g_sumsq[col] * inv_n - mean * mean;
    const float inv_s = rsqrtf(var + BN_EPS);
    float v = (X[idx] - mean) * inv_s * gamma[col] + beta[col];
    X[idx] = fmaxf(v, 0.0f);
}

// ---------------------------------------------------------------------------
// Launch
// inputs: 0 h_states [1,4096,64] f32 | 1 seq_start_end [64,2] i32
//         2 end_pos [4096,2] f32    | 3 rel_pos [4096,2] f32 (unused)
//         4 W [4096,1024] f32       | 5 b [1024] f32
//         6 gamma [1024] f32        | 7 beta [1024] f32
// output: [4096,1024] f32
// ---------------------------------------------------------------------------
extern "C" void kernel_launch(void* const* d_in, const int* in_sizes, int n_in,
                              void* d_out, int out_size)
{
    const float* h_states = (const float*)d_in[0];
    const float* end_pos  = (const float*)d_in[2];
    const float* W        = (const float*)d_in[4];
    const float* b        = (const float*)d_in[5];
    const float* gamma    = (const float*)d_in[6];
    const float* beta     = (const float*)d_in[7];
    float* X = (float*)d_out;

    float* pool_ptr;
    cudaGetSymbolAddress((void**)&pool_ptr, g_pool);

    pool_kernel<<<BATCH, 64>>>(h_states, end_pos);

    dim3 ggrid(NB / BN_T, BATCH / BM);   // (8, 32)
    gemm_kernel<<<ggrid, 256>>>(pool_ptr, W, b, X);

    zero_stats_kernel<<<4, 256>>>();

    dim3 sgrid(NB / 256, BATCH / 128);   // (4, 32)
    stats_kernel<<<sgrid, 256>>>(X);

    apply_kernel<<<(size_t)BATCH * NB / 256, 256>>>(X, gamma, beta);
}

// round 5
// speedup vs baseline: 5.0089x; 5.0089x over previous
#include <cuda_runtime.h>
#include <cuda_fp16.h>
#include <cstdint>
#include <math.h>

// ---------------- problem constants ----------------
#define BATCH  4096
#define NPED   64
#define HD     64
#define G2     64
#define KDIM   4096
#define NB     1024
#define BN_EPS 1e-5f

// ---------------- GEMM tiling ----------------
#define BM 128
#define BNv 128
#define BK 32
#define NK (KDIM / BK)          // 128
#define STAGES 4
#define ROWB 80                 // padded row bytes (32 halves + 8 pad)
#define STAGE_BYTES (2 * 128 * ROWB)   // A tile + B tile = 20480
#define GEMM_SMEM (STAGES * STAGE_BYTES)  // 81920

// ---------------- device scratch ----------------
__device__ __half g_A [(size_t)BATCH * KDIM];   // pooled features, fp16
__device__ __half g_Bt[(size_t)NB * KDIM];      // W^T (K-major), fp16
__device__ float  g_sum[NB];
__device__ float  g_sumsq[NB];

// ---------------- PTX helpers ----------------
__device__ __forceinline__ uint32_t smem_u32(const void* p) {
    uint32_t a;
    asm("{ .reg .u64 t; cvta.to.shared.u64 t, %1; cvt.u32.u64 %0, t; }"
        : "=r"(a) : "l"(p));
    return a;
}

__device__ __forceinline__ void cp16(uint32_t dst, const void* src) {
    asm volatile("cp.async.cg.shared.global [%0], [%1], 16;"
                 :: "r"(dst), "l"(src) : "memory");
}

#define CP_COMMIT() asm volatile("cp.async.commit_group;" ::: "memory")
#define CP_WAIT(n)  asm volatile("cp.async.wait_group %0;" :: "n"(n) : "memory")

#define LDM4(r0, r1, r2, r3, a)                                         \
    asm volatile("ldmatrix.sync.aligned.m8n8.x4.shared.b16 "            \
                 "{%0,%1,%2,%3}, [%4];"                                 \
                 : "=r"(r0), "=r"(r1), "=r"(r2), "=r"(r3) : "r"(a))

#define MMA16816(c, a, b)                                               \
    asm volatile("mma.sync.aligned.m16n8k16.row.col.f32.f16.f16.f32 "   \
                 "{%0,%1,%2,%3}, {%4,%5,%6,%7}, {%8,%9}, {%0,%1,%2,%3};"\
                 : "+f"((c)[0]), "+f"((c)[1]), "+f"((c)[2]), "+f"((c)[3])\
                 : "r"((a)[0]), "r"((a)[1]), "r"((a)[2]), "r"((a)[3]),  \
                   "r"((b)[0]), "r"((b)[1]))

// ---------------------------------------------------------------------------
// Kernel 1: social pooling -> fp16 A rows
// ---------------------------------------------------------------------------
__global__ __launch_bounds__(64) void pool_kernel(
    const float* __restrict__ h,
    const float* __restrict__ pos)
{
    __shared__ float sp[G2 * HD];
    __shared__ float2 spos[NPED];

    const int i    = blockIdx.x;
    const int base = (i / NPED) * NPED;
    const int t    = threadIdx.x;

    for (int k = t; k < G2 * HD; k += 64) sp[k] = 0.0f;
    spos[t] = reinterpret_cast<const float2*>(pos)[base + t];
    __syncthreads();

    const int local_i = i - base;
    const float2 pi = spos[local_i];
    const float tlx = pi.x - 1.0f, tly = pi.y + 1.0f;
    const float brx = pi.x + 1.0f, bry = pi.y - 1.0f;

    for (int j = 0; j < NPED; ++j) {
        if (j == local_i) continue;
        const float2 pj = spos[j];
        if (pj.x >= brx || pj.x <= tlx || pj.y >= tly || pj.y <= bry) continue;
        int cx = (int)floorf((pj.x - tlx) / 2.0f * 8.0f);
        int cy = (int)floorf((tly - pj.y) / 2.0f * 8.0f);
        int cell = min(max(cx + cy * 8, 0), G2 - 1);
        sp[cell * HD + t] += h[(size_t)(base + j) * HD + t];
    }
    __syncthreads();

    const size_t ro = (size_t)i * KDIM;
    for (int k = t; k < G2 * HD; k += 64)
        g_A[ro + k] = __float2half(sp[k]);
}

// ---------------------------------------------------------------------------
// Kernel 2: W [K,N] f32 -> W^T [N,K] fp16
// ---------------------------------------------------------------------------
__global__ __launch_bounds__(256) void wsplit_kernel(const float* __restrict__ W)
{
    __shared__ float tile[32][33];
    const int n0 = blockIdx.x * 32;
    const int k0 = blockIdx.y * 32;
    const int tx = threadIdx.x, ty = threadIdx.y;   // 32 x 8

#pragma unroll
    for (int i = 0; i < 4; ++i) {
        int k = ty + i * 8;
        tile[k][tx] = W[(size_t)(k0 + k) * NB + n0 + tx];
    }
    __syncthreads();
#pragma unroll
    for (int i = 0; i < 4; ++i) {
        int n = ty + i * 8;
        g_Bt[(size_t)(n0 + n) * KDIM + k0 + tx] = __float2half(tile[tx][n]);
    }
}

// ---------------------------------------------------------------------------
// Kernel 3: fp16 mma.sync GEMM  X = A * W + b
// CTA 128x128, BK=32, 4-stage cp.async pipeline.
// Warps: 2(M) x 4(N); warp tile 64x32; m16n8k16 HMMA, f32 accum.
// ---------------------------------------------------------------------------
__global__ __launch_bounds__(256) void gemm_kernel(
    const __half* __restrict__ A,   // [BATCH, KDIM]
    const __half* __restrict__ Bt,  // [NB, KDIM]
    const float* __restrict__ bias,
    float* __restrict__ X)          // [BATCH, NB]
{
    extern __shared__ __align__(16) char dsm[];
    const uint32_t sbase = smem_u32(dsm);
    const int t    = threadIdx.x;
    const int warp = t >> 5, lane = t & 31;
    const int m0 = blockIdx.y * BM;
    const int n0 = blockIdx.x * BNv;
    const int warp_m = warp & 1;     // 0..1 -> 64-row slab
    const int warp_n = warp >> 1;    // 0..3 -> 32-col slab

    float acc[4][4][4];
#pragma unroll
    for (int i = 0; i < 4; ++i)
#pragma unroll
        for (int j = 0; j < 4; ++j)
#pragma unroll
            for (int e = 0; e < 4; ++e) acc[i][j][e] = 0.0f;

    // loader mapping: 512 16B-chunks per (A|B) tile, 2 per thread each
    const int lrow = t >> 2;          // 0..63
    const int lcol = (t & 3) * 8;     // half offset within row

    auto load_stage = [&](int s, int kt) {
        const int kk = kt * BK;
        const uint32_t sA = sbase + (uint32_t)s * STAGE_BYTES;
        const uint32_t sB = sA + 128 * ROWB;
#pragma unroll
        for (int hh = 0; hh < 2; ++hh) {
            const int r = lrow + hh * 64;
            cp16(sA + r * ROWB + lcol * 2, A  + (size_t)(m0 + r) * KDIM + kk + lcol);
            cp16(sB + r * ROWB + lcol * 2, Bt + (size_t)(n0 + r) * KDIM + kk + lcol);
        }
    };

    // prologue: stages 0..STAGES-2
#pragma unroll
    for (int s = 0; s < STAGES - 1; ++s) {
        load_stage(s, s);
        CP_COMMIT();
    }

    const int q  = lane >> 3;   // 0..3
    const int lr = lane & 7;

    for (int kt = 0; kt < NK; ++kt) {
        CP_WAIT(STAGES - 2);          // stage kt resident
        __syncthreads();

        if (kt + STAGES - 1 < NK)
            load_stage((kt + STAGES - 1) % STAGES, kt + STAGES - 1);
        CP_COMMIT();

        const uint32_t sA = sbase + (uint32_t)(kt % STAGES) * STAGE_BYTES;
        const uint32_t sB = sA + 128 * ROWB;

#pragma unroll
        for (int ks = 0; ks < 2; ++ks) {
            uint32_t aF[4][4];
            uint32_t bF[4][2];
#pragma unroll
            for (int mi = 0; mi < 4; ++mi) {
                const int row  = warp_m * 64 + mi * 16 + (q & 1) * 8 + lr;
                const int colh = ks * 16 + (q >> 1) * 8;
                LDM4(aF[mi][0], aF[mi][1], aF[mi][2], aF[mi][3],
                     sA + row * ROWB + colh * 2);
            }
#pragma unroll
            for (int pi = 0; pi < 2; ++pi) {
                const int row  = warp_n * 32 + pi * 16 + (q >> 1) * 8 + lr;
                const int colh = ks * 16 + (q & 1) * 8;
                uint32_t r0, r1, r2, r3;
                LDM4(r0, r1, r2, r3, sB + row * ROWB + colh * 2);
                bF[pi * 2 + 0][0] = r0;  bF[pi * 2 + 0][1] = r1;
                bF[pi * 2 + 1][0] = r2;  bF[pi * 2 + 1][1] = r3;
            }
#pragma unroll
            for (int mi = 0; mi < 4; ++mi)
#pragma unroll
                for (int ni = 0; ni < 4; ++ni)
                    MMA16816(acc[mi][ni], aF[mi], bF[ni]);
        }
        __syncthreads();              // protect stage about to be overwritten
    }

    // epilogue: bias add + store
    const int er = lane >> 2;         // 0..7
    const int ec = (lane & 3) * 2;
#pragma unroll
    for (int mi = 0; mi < 4; ++mi) {
        const int mrow = m0 + warp_m * 64 + mi * 16 + er;
#pragma unroll
        for (int ni = 0; ni < 4; ++ni) {
            const int n = n0 + warp_n * 32 + ni * 8 + ec;
            const float b0 = bias[n], b1 = bias[n + 1];
            float2 v0 = make_float2(acc[mi][ni][0] + b0, acc[mi][ni][1] + b1);
            float2 v1 = make_float2(acc[mi][ni][2] + b0, acc[mi][ni][3] + b1);
            *reinterpret_cast<float2*>(&X[(size_t)mrow * NB + n])       = v0;
            *reinterpret_cast<float2*>(&X[(size_t)(mrow + 8) * NB + n]) = v1;
        }
    }
}

// ---------------------------------------------------------------------------
// BN stats + apply
// ---------------------------------------------------------------------------
__global__ void zero_stats_kernel()
{
    int t = blockIdx.x * blockDim.x + threadIdx.x;
    if (t < NB) { g_sum[t] = 0.0f; g_sumsq[t] = 0.0f; }
}

__global__ __launch_bounds__(256) void stats_kernel(const float* __restrict__ X)
{
    const int c4 = threadIdx.x;             // float4 column group
    const int r0 = blockIdx.x * 128;
    float4 s  = {0, 0, 0, 0};
    float4 ss = {0, 0, 0, 0};
    for (int r = r0; r < r0 + 128; ++r) {
        float4 v = reinterpret_cast<const float4*>(X + (size_t)r * NB)[c4];
        s.x += v.x; s.y += v.y; s.z += v.z; s.w += v.w;
        ss.x += v.x * v.x; ss.y += v.y * v.y; ss.z += v.z * v.z; ss.w += v.w * v.w;
    }
    const int c = c4 * 4;
    atomicAdd(&g_sum[c + 0], s.x);    atomicAdd(&g_sum[c + 1], s.y);
    atomicAdd(&g_sum[c + 2], s.z);    atomicAdd(&g_sum[c + 3], s.w);
    atomicAdd(&g_sumsq[c + 0], ss.x); atomicAdd(&g_sumsq[c + 1], ss.y);
    atomicAdd(&g_sumsq[c + 2], ss.z); atomicAdd(&g_sumsq[c + 3], ss.w);
}

__global__ __launch_bounds__(256) void apply_kernel(
    float* __restrict__ X,
    const float* __restrict__ gamma,
    const float* __restrict__ beta)
{
    const int idx = blockIdx.x * 256 + threadIdx.x;
    const int col = idx % NB;
    const float inv_n = 1.0f / (float)BATCH;
    const float mean  = g_sum[col] * inv_n;
    const float var   = g_sumsq[col] * inv_n - mean * mean;
    const float inv_s = rsqrtf(var + BN_EPS);
    float v = (X[idx] - mean) * inv_s * gamma[col] + beta[col];
    X[idx] = fmaxf(v, 0.0f);
}

// ---------------------------------------------------------------------------
// launch
// ---------------------------------------------------------------------------
extern "C" void kernel_launch(void* const* d_in, const int* in_sizes, int n_in,
                              void* d_out, int out_size)
{
    const float* h_states = (const float*)d_in[0];
    const float* end_pos  = (const float*)d_in[2];
    const float* W        = (const float*)d_in[4];
    const float* b        = (const float*)d_in[5];
    const float* gamma    = (const float*)d_in[6];
    const float* beta     = (const float*)d_in[7];
    float* X = (float*)d_out;

    __half *Ap, *Btp;
    cudaGetSymbolAddress((void**)&Ap,  g_A);
    cudaGetSymbolAddress((void**)&Btp, g_Bt);

    cudaFuncSetAttribute(gemm_kernel,
                         cudaFuncAttributeMaxDynamicSharedMemorySize, GEMM_SMEM);

    pool_kernel<<<BATCH, 64>>>(h_states, end_pos);
    wsplit_kernel<<<dim3(NB / 32, KDIM / 32), dim3(32, 8)>>>(W);

    gemm_kernel<<<dim3(NB / BNv, BATCH / BM), 256, GEMM_SMEM>>>(Ap, Btp, b, X);

    zero_stats_kernel<<<4, 256>>>();
    stats_kernel<<<BATCH / 128, 256>>>(X);
    apply_kernel<<<(BATCH * NB) / 256, 256>>>(X, gamma, beta);
}

// round 7
// speedup vs baseline: 5.6916x; 1.1363x over previous
#include <cuda_runtime.h>
#include <cuda_fp16.h>
#include <cstdint>
#include <math.h>

// ---------------- problem constants ----------------
#define BATCH  4096
#define NPED   64
#define HD     64
#define G2     64
#define KDIM   4096
#define NB     1024
#define BN_EPS 1e-5f

// ---------------- GEMM tiling ----------------
#define BM 128
#define BNv 256
#define BK 32
#define NK (KDIM / BK)          // 128
#define STAGES 4
#define ROWB 80                 // padded row bytes (32 halves + 8 pad)
#define A_ROWS 128
#define B_ROWS 256
#define STAGE_BYTES ((A_ROWS + B_ROWS) * ROWB)   // 30720
#define GEMM_SMEM (STAGES * STAGE_BYTES)         // 122880

// ---------------- device scratch ----------------
__device__ __half g_A [(size_t)BATCH * KDIM];   // pooled features, fp16
__device__ __half g_Bt[(size_t)NB * KDIM];      // W^T (K-major), fp16
__device__ float  g_sum[NB];
__device__ float  g_sumsq[NB];

// ---------------- PTX helpers ----------------
__device__ __forceinline__ uint32_t smem_u32(const void* p) {
    uint32_t a;
    asm("{ .reg .u64 t; cvta.to.shared.u64 t, %1; cvt.u32.u64 %0, t; }"
        : "=r"(a) : "l"(p));
    return a;
}

__device__ __forceinline__ void cp16(uint32_t dst, const void* src) {
    asm volatile("cp.async.cg.shared.global [%0], [%1], 16;"
                 :: "r"(dst), "l"(src) : "memory");
}

#define CP_COMMIT() asm volatile("cp.async.commit_group;" ::: "memory")
#define CP_WAIT(n)  asm volatile("cp.async.wait_group %0;" :: "n"(n) : "memory")

#define LDM4(r0, r1, r2, r3, a)                                         \
    asm volatile("ldmatrix.sync.aligned.m8n8.x4.shared.b16 "            \
                 "{%0,%1,%2,%3}, [%4];"                                 \
                 : "=r"(r0), "=r"(r1), "=r"(r2), "=r"(r3) : "r"(a))

#define MMA16816(c, a, b)                                               \
    asm volatile("mma.sync.aligned.m16n8k16.row.col.f32.f16.f16.f32 "   \
                 "{%0,%1,%2,%3}, {%4,%5,%6,%7}, {%8,%9}, {%0,%1,%2,%3};"\
                 : "+f"((c)[0]), "+f"((c)[1]), "+f"((c)[2]), "+f"((c)[3])\
                 : "r"((a)[0]), "r"((a)[1]), "r"((a)[2]), "r"((a)[3]),  \
                   "r"((b)[0]), "r"((b)[1]))

// ---------------------------------------------------------------------------
// Kernel 1: social pooling -> fp16 A rows (+ zero BN accumulators)
// ---------------------------------------------------------------------------
__global__ __launch_bounds__(64) void pool_kernel(
    const float* __restrict__ h,
    const float* __restrict__ pos)
{
    __shared__ float sp[G2 * HD];
    __shared__ float2 spos[NPED];

    const int i    = blockIdx.x;
    const int base = (i / NPED) * NPED;
    const int t    = threadIdx.x;

    // fold BN-stat zeroing into this (earlier) kernel: blocks 0..15
    if (i < 16) {
        g_sum  [i * 64 + t] = 0.0f;
        g_sumsq[i * 64 + t] = 0.0f;
    }

    for (int k = t; k < G2 * HD; k += 64) sp[k] = 0.0f;
    spos[t] = reinterpret_cast<const float2*>(pos)[base + t];
    __syncthreads();

    const int local_i = i - base;
    const float2 pi = spos[local_i];
    const float tlx = pi.x - 1.0f, tly = pi.y + 1.0f;
    const float brx = pi.x + 1.0f, bry = pi.y - 1.0f;

    for (int j = 0; j < NPED; ++j) {
        if (j == local_i) continue;
        const float2 pj = spos[j];
        if (pj.x >= brx || pj.x <= tlx || pj.y >= tly || pj.y <= bry) continue;
        int cx = (int)floorf((pj.x - tlx) / 2.0f * 8.0f);
        int cy = (int)floorf((tly - pj.y) / 2.0f * 8.0f);
        int cell = min(max(cx + cy * 8, 0), G2 - 1);
        sp[cell * HD + t] += h[(size_t)(base + j) * HD + t];
    }
    __syncthreads();

    const size_t ro = (size_t)i * KDIM;
    for (int k = t; k < G2 * HD; k += 64)
        g_A[ro + k] = __float2half(sp[k]);
}

// ---------------------------------------------------------------------------
// Kernel 2: W [K,N] f32 -> W^T [N,K] fp16
// ---------------------------------------------------------------------------
__global__ __launch_bounds__(256) void wsplit_kernel(const float* __restrict__ W)
{
    __shared__ float tile[32][33];
    const int n0 = blockIdx.x * 32;
    const int k0 = blockIdx.y * 32;
    const int tx = threadIdx.x, ty = threadIdx.y;   // 32 x 8

#pragma unroll
    for (int i = 0; i < 4; ++i) {
        int k = ty + i * 8;
        tile[k][tx] = W[(size_t)(k0 + k) * NB + n0 + tx];
    }
    __syncthreads();
#pragma unroll
    for (int i = 0; i < 4; ++i) {
        int n = ty + i * 8;
        g_Bt[(size_t)(n0 + n) * KDIM + k0 + tx] = __float2half(tile[tx][n]);
    }
}

// ---------------------------------------------------------------------------
// Kernel 3: fp16 mma.sync GEMM  X = A * W + b, fused BN column stats
// CTA 128x256 (grid 4x32 = 128 CTAs = one wave), BK=32, 4-stage cp.async.
// Warps: 2(M) x 4(N); warp tile 64x64.
// ---------------------------------------------------------------------------
__global__ __launch_bounds__(256) void gemm_kernel(
    const __half* __restrict__ A,   // [BATCH, KDIM]
    const __half* __restrict__ Bt,  // [NB, KDIM]
    const float* __restrict__ bias,
    float* __restrict__ X)          // [BATCH, NB]
{
    extern __shared__ __align__(16) char dsm[];
    const uint32_t sbase = smem_u32(dsm);
    const int t    = threadIdx.x;
    const int warp = t >> 5, lane = t & 31;
    const int m0 = blockIdx.y * BM;
    const int n0 = blockIdx.x * BNv;
    const int warp_m = warp & 1;     // 64-row slab
    const int warp_n = warp >> 1;    // 64-col slab

    float acc[4][8][4];
#pragma unroll
    for (int i = 0; i < 4; ++i)
#pragma unroll
        for (int j = 0; j < 8; ++j)
#pragma unroll
            for (int e = 0; e < 4; ++e) acc[i][j][e] = 0.0f;

    auto load_stage = [&](int s, int kt) {
        const int kk = kt * BK;
        const uint32_t sA = sbase + (uint32_t)s * STAGE_BYTES;
        const uint32_t sB = sA + A_ROWS * ROWB;
        // A tile: 128 rows -> 512 16B chunks, 2/thread
#pragma unroll
        for (int i = 0; i < 2; ++i) {
            const int id = t + i * 256;
            const int r = id >> 2, c = (id & 3) * 8;
            cp16(sA + r * ROWB + c * 2, A + (size_t)(m0 + r) * KDIM + kk + c);
        }
        // B tile: 256 rows -> 1024 chunks, 4/thread
#pragma unroll
        for (int i = 0; i < 4; ++i) {
            const int id = t + i * 256;
            const int r = id >> 2, c = (id & 3) * 8;
            cp16(sB + r * ROWB + c * 2, Bt + (size_t)(n0 + r) * KDIM + kk + c);
        }
    };

#pragma unroll
    for (int s = 0; s < STAGES - 1; ++s) {
        load_stage(s, s);
        CP_COMMIT();
    }

    const int q  = lane >> 3;   // 0..3
    const int lr = lane & 7;

    for (int kt = 0; kt < NK; ++kt) {
        CP_WAIT(STAGES - 2);
        __syncthreads();

        if (kt + STAGES - 1 < NK)
            load_stage((kt + STAGES - 1) % STAGES, kt + STAGES - 1);
        CP_COMMIT();

        const uint32_t sA = sbase + (uint32_t)(kt % STAGES) * STAGE_BYTES;
        const uint32_t sB = sA + A_ROWS * ROWB;

#pragma unroll
        for (int ks = 0; ks < 2; ++ks) {
            uint32_t aF[4][4];
            uint32_t bF[8][2];
#pragma unroll
            for (int mi = 0; mi < 4; ++mi) {
                const int row  = warp_m * 64 + mi * 16 + (q & 1) * 8 + lr;
                const int colh = ks * 16 + (q >> 1) * 8;
                LDM4(aF[mi][0], aF[mi][1], aF[mi][2], aF[mi][3],
                     sA + row * ROWB + colh * 2);
            }
#pragma unroll
            for (int pi = 0; pi < 4; ++pi) {
                const int row  = warp_n * 64 + pi * 16 + (q >> 1) * 8 + lr;
                const int colh = ks * 16 + (q & 1) * 8;
                uint32_t r0, r1, r2, r3;
                LDM4(r0, r1, r2, r3, sB + row * ROWB + colh * 2);
                bF[pi * 2 + 0][0] = r0;  bF[pi * 2 + 0][1] = r1;
                bF[pi * 2 + 1][0] = r2;  bF[pi * 2 + 1][1] = r3;
            }
#pragma unroll
            for (int mi = 0; mi < 4; ++mi)
#pragma unroll
                for (int ni = 0; ni < 8; ++ni)
                    MMA16816(acc[mi][ni], aF[mi], bF[ni]);
        }
        __syncthreads();
    }

    // epilogue: bias add, store, fused column sum/sumsq (64 rows per warp)
    const int er = lane >> 2;         // 0..7
    const int ec = (lane & 3) * 2;
#pragma unroll
    for (int ni = 0; ni < 8; ++ni) {
        const int n  = n0 + warp_n * 64 + ni * 8 + ec;
        const float b0 = bias[n], b1 = bias[n + 1];
        float s0 = 0.f, s1 = 0.f, q0 = 0.f, q1 = 0.f;
#pragma unroll
        for (int mi = 0; mi < 4; ++mi) {
            const int mrow = m0 + warp_m * 64 + mi * 16 + er;
            float v0 = acc[mi][ni][0] + b0;
            float v1 = acc[mi][ni][1] + b1;
            float v2 = acc[mi][ni][2] + b0;
            float v3 = acc[mi][ni][3] + b1;
            *reinterpret_cast<float2*>(&X[(size_t)mrow * NB + n]) =
                make_float2(v0, v1);
            *reinterpret_cast<float2*>(&X[(size_t)(mrow + 8) * NB + n]) =
                make_float2(v2, v3);
            s0 += v0 + v2;           s1 += v1 + v3;
            q0 += v0 * v0 + v2 * v2; q1 += v1 * v1 + v3 * v3;
        }
#pragma unroll
        for (int off = 4; off < 32; off <<= 1) {
            s0 += __shfl_xor_sync(0xFFFFFFFFu, s0, off);
            s1 += __shfl_xor_sync(0xFFFFFFFFu, s1, off);
            q0 += __shfl_xor_sync(0xFFFFFFFFu, q0, off);
            q1 += __shfl_xor_sync(0xFFFFFFFFu, q1, off);
        }
        if (er == 0) {
            atomicAdd(&g_sum[n],       s0);
            atomicAdd(&g_sum[n + 1],   s1);
            atomicAdd(&g_sumsq[n],     q0);
            atomicAdd(&g_sumsq[n + 1], q1);
        }
    }
}

// ---------------------------------------------------------------------------
// Kernel 4: batchnorm + ReLU, float4-vectorized, in place
// ---------------------------------------------------------------------------
__global__ __launch_bounds__(256) void apply_kernel(
    float* __restrict__ X,
    const float* __restrict__ gamma,
    const float* __restrict__ beta)
{
    const int i4 = blockIdx.x * 256 + threadIdx.x;   // float4 index
    const int c4 = i4 & (NB / 4 - 1);                // column group
    const float inv_n = 1.0f / (float)BATCH;

    float4 s  = reinterpret_cast<const float4*>(g_sum)[c4];
    float4 ss = reinterpret_cast<const float4*>(g_sumsq)[c4];
    float4 g  = reinterpret_cast<const float4*>(gamma)[c4];
    float4 be = reinterpret_cast<const float4*>(beta)[c4];
    float4 v  = reinterpret_cast<float4*>(X)[i4];

    float m, is;
    m = s.x * inv_n; is = rsqrtf(ss.x * inv_n - m * m + BN_EPS);
    v.x = fmaxf((v.x - m) * is * g.x + be.x, 0.0f);
    m = s.y * inv_n; is = rsqrtf(ss.y * inv_n - m * m + BN_EPS);
    v.y = fmaxf((v.y - m) * is * g.y + be.y, 0.0f);
    m = s.z * inv_n; is = rsqrtf(ss.z * inv_n - m * m + BN_EPS);
    v.z = fmaxf((v.z - m) * is * g.z + be.z, 0.0f);
    m = s.w * inv_n; is = rsqrtf(ss.w * inv_n - m * m + BN_EPS);
    v.w = fmaxf((v.w - m) * is * g.w + be.w, 0.0f);

    reinterpret_cast<float4*>(X)[i4] = v;
}

// ---------------------------------------------------------------------------
// launch
// ---------------------------------------------------------------------------
extern "C" void kernel_launch(void* const* d_in, const int* in_sizes, int n_in,
                              void* d_out, int out_size)
{
    const float* h_states = (const float*)d_in[0];
    const float* end_pos  = (const float*)d_in[2];
    const float* W        = (const float*)d_in[4];
    const float* b        = (const float*)d_in[5];
    const float* gamma    = (const float*)d_in[6];
    const float* beta     = (const float*)d_in[7];
    float* X = (float*)d_out;

    __half *Ap, *Btp;
    cudaGetSymbolAddress((void**)&Ap,  g_A);
    cudaGetSymbolAddress((void**)&Btp, g_Bt);

    cudaFuncSetAttribute(gemm_kernel,
                         cudaFuncAttributeMaxDynamicSharedMemorySize, GEMM_SMEM);

    pool_kernel<<<BATCH, 64>>>(h_states, end_pos);
    wsplit_kernel<<<dim3(NB / 32, KDIM / 32), dim3(32, 8)>>>(W);

    gemm_kernel<<<dim3(NB / BNv, BATCH / BM), 256, GEMM_SMEM>>>(Ap, Btp, b, X);

    apply_kernel<<<(BATCH * NB / 4) / 256, 256>>>(X, gamma, beta);
}

// round 9
// speedup vs baseline: 5.8791x; 1.0329x over previous
#include <cuda_runtime.h>
#include <cuda_fp16.h>
#include <cstdint>
#include <math.h>

// ---------------- problem constants ----------------
#define BATCH  4096
#define NPED   64
#define HD     64
#define G2     64
#define KDIM   4096
#define NB     1024
#define BN_EPS 1e-5f

// ---------------- GEMM tiling ----------------
#define BM 128
#define BNv 256
#define BK 64                   // two 32-half panels per stage
#define NK2 (KDIM / BK)         // 64 iterations
#define STAGES 3
#define ROWB 80                 // padded panel row bytes (32 halves + 8 pad)
#define A_PANEL (128 * ROWB)    // 10240
#define B_PANEL (256 * ROWB)    // 20480
#define A_BYTES (2 * A_PANEL)   // 20480
#define B_BYTES (2 * B_PANEL)   // 40960
#define STAGE_BYTES (A_BYTES + B_BYTES)          // 61440
#define GEMM_SMEM (STAGES * STAGE_BYTES)         // 184320

// ---------------- device scratch ----------------
__device__ __half g_A [(size_t)BATCH * KDIM];   // pooled features, fp16
__device__ __half g_Bt[(size_t)NB * KDIM];      // W^T (K-major), fp16
__device__ float  g_sum[NB];
__device__ float  g_sumsq[NB];

// ---------------- PTX helpers ----------------
__device__ __forceinline__ uint32_t smem_u32(const void* p) {
    uint32_t a;
    asm("{ .reg .u64 t; cvta.to.shared.u64 t, %1; cvt.u32.u64 %0, t; }"
        : "=r"(a) : "l"(p));
    return a;
}

__device__ __forceinline__ void cp16(uint32_t dst, const void* src) {
    asm volatile("cp.async.cg.shared.global [%0], [%1], 16;"
                 :: "r"(dst), "l"(src) : "memory");
}

#define CP_COMMIT() asm volatile("cp.async.commit_group;" ::: "memory")
#define CP_WAIT(n)  asm volatile("cp.async.wait_group %0;" :: "n"(n) : "memory")

#define LDM4(r0, r1, r2, r3, a)                                         \
    asm volatile("ldmatrix.sync.aligned.m8n8.x4.shared.b16 "            \
                 "{%0,%1,%2,%3}, [%4];"                                 \
                 : "=r"(r0), "=r"(r1), "=r"(r2), "=r"(r3) : "r"(a))

#define MMA16816(c, a, b)                                               \
    asm volatile("mma.sync.aligned.m16n8k16.row.col.f32.f16.f16.f32 "   \
                 "{%0,%1,%2,%3}, {%4,%5,%6,%7}, {%8,%9}, {%0,%1,%2,%3};"\
                 : "+f"((c)[0]), "+f"((c)[1]), "+f"((c)[2]), "+f"((c)[3])\
                 : "r"((a)[0]), "r"((a)[1]), "r"((a)[2]), "r"((a)[3]),  \
                   "r"((b)[0]), "r"((b)[1]))

// ---------------------------------------------------------------------------
// Kernel 1: social pooling -> fp16 A rows (+ zero BN accumulators)
// ---------------------------------------------------------------------------
__global__ __launch_bounds__(64) void pool_kernel(
    const float* __restrict__ h,
    const float* __restrict__ pos)
{
    __shared__ float sp[G2 * HD];
    __shared__ float2 spos[NPED];

    const int i    = blockIdx.x;
    const int base = (i / NPED) * NPED;
    const int t    = threadIdx.x;

    if (i < 16) {
        g_sum  [i * 64 + t] = 0.0f;
        g_sumsq[i * 64 + t] = 0.0f;
    }

    for (int k = t; k < G2 * HD; k += 64) sp[k] = 0.0f;
    spos[t] = reinterpret_cast<const float2*>(pos)[base + t];
    __syncthreads();

    const int local_i = i - base;
    const float2 pi = spos[local_i];
    const float tlx = pi.x - 1.0f, tly = pi.y + 1.0f;
    const float brx = pi.x + 1.0f, bry = pi.y - 1.0f;

    for (int j = 0; j < NPED; ++j) {
        if (j == local_i) continue;
        const float2 pj = spos[j];
        if (pj.x >= brx || pj.x <= tlx || pj.y >= tly || pj.y <= bry) continue;
        int cx = (int)floorf((pj.x - tlx) / 2.0f * 8.0f);
        int cy = (int)floorf((tly - pj.y) / 2.0f * 8.0f);
        int cell = min(max(cx + cy * 8, 0), G2 - 1);
        sp[cell * HD + t] += h[(size_t)(base + j) * HD + t];
    }
    __syncthreads();

    const size_t ro = (size_t)i * KDIM;
    for (int k = t; k < G2 * HD; k += 64)
        g_A[ro + k] = __float2half(sp[k]);
}

// ---------------------------------------------------------------------------
// Kernel 2: W [K,N] f32 -> W^T [N,K] fp16
// ---------------------------------------------------------------------------
__global__ __launch_bounds__(256) void wsplit_kernel(const float* __restrict__ W)
{
    __shared__ float tile[32][33];
    const int n0 = blockIdx.x * 32;
    const int k0 = blockIdx.y * 32;
    const int tx = threadIdx.x, ty = threadIdx.y;   // 32 x 8

#pragma unroll
    for (int i = 0; i < 4; ++i) {
        int k = ty + i * 8;
        tile[k][tx] = W[(size_t)(k0 + k) * NB + n0 + tx];
    }
    __syncthreads();
#pragma unroll
    for (int i = 0; i < 4; ++i) {
        int n = ty + i * 8;
        g_Bt[(size_t)(n0 + n) * KDIM + k0 + tx] = __float2half(tile[tx][n]);
    }
}

// ---------------------------------------------------------------------------
// Kernel 3: fp16 mma.sync GEMM  X = A * W + b, fused BN column stats
// CTA 128x256 (128 CTAs = one wave), BK=64 (2 panels), 3-stage cp.async,
// ONE __syncthreads per K-iteration. Warps 2(M) x 4(N), warp tile 64x64.
// ---------------------------------------------------------------------------
__global__ __launch_bounds__(256) void gemm_kernel(
    const __half* __restrict__ A,   // [BATCH, KDIM]
    const __half* __restrict__ Bt,  // [NB, KDIM]
    const float* __restrict__ bias,
    float* __restrict__ X)          // [BATCH, NB]
{
    extern __shared__ __align__(16) char dsm[];
    const uint32_t sbase = smem_u32(dsm);
    const int t    = threadIdx.x;
    const int warp = t >> 5, lane = t & 31;
    const int m0 = blockIdx.y * BM;
    const int n0 = blockIdx.x * BNv;
    const int warp_m = warp & 1;     // 64-row slab
    const int warp_n = warp >> 1;    // 64-col slab

    float acc[4][8][4];
#pragma unroll
    for (int i = 0; i < 4; ++i)
#pragma unroll
        for (int j = 0; j < 8; ++j)
#pragma unroll
            for (int e = 0; e < 4; ++e) acc[i][j][e] = 0.0f;

    // loader: 64 halves/row = 8 chunks of 16B; panel = chunk>>2
    auto load_stage = [&](int s, int kt) {
        const int kk = kt * BK;
        const uint32_t S  = sbase + (uint32_t)s * STAGE_BYTES;
        const uint32_t SB = S + A_BYTES;
        // A: 128 rows x 8 chunks = 1024 chunks, 4/thread
#pragma unroll
        for (int i = 0; i < 4; ++i) {
            const int id = t + i * 256;
            const int r = id >> 3, c8 = id & 7;
            cp16(S + (c8 >> 2) * A_PANEL + r * ROWB + (c8 & 3) * 16,
                 A + (size_t)(m0 + r) * KDIM + kk + c8 * 8);
        }
        // B: 256 rows x 8 chunks = 2048 chunks, 8/thread
#pragma unroll
        for (int i = 0; i < 8; ++i) {
            const int id = t + i * 256;
            const int r = id >> 3, c8 = id & 7;
            cp16(SB + (c8 >> 2) * B_PANEL + r * ROWB + (c8 & 3) * 16,
                 Bt + (size_t)(n0 + r) * KDIM + kk + c8 * 8);
        }
    };

    load_stage(0, 0); CP_COMMIT();
    load_stage(1, 1); CP_COMMIT();

    const int q  = lane >> 3;   // 0..3
    const int lr = lane & 7;

    int cur = 0;                // stage holding iteration kt
    for (int kt = 0; kt < NK2; ++kt) {
        CP_WAIT(1);             // stage kt resident
        __syncthreads();        // all warps done with stage being overwritten

        if (kt + 2 < NK2) {
            load_stage((cur + 2) % STAGES, kt + 2);
        }
        CP_COMMIT();

        const uint32_t S  = sbase + (uint32_t)cur * STAGE_BYTES;
        const uint32_t SB = S + A_BYTES;

#pragma unroll
        for (int ks = 0; ks < 4; ++ks) {
            const uint32_t pA = S  + (ks >> 1) * A_PANEL;
            const uint32_t pB = SB + (ks >> 1) * B_PANEL;
            const int kc = (ks & 1) * 16;
            uint32_t aF[4][4];
            uint32_t bF[8][2];
#pragma unroll
            for (int mi = 0; mi < 4; ++mi) {
                const int row  = warp_m * 64 + mi * 16 + (q & 1) * 8 + lr;
                const int colh = kc + (q >> 1) * 8;
                LDM4(aF[mi][0], aF[mi][1], aF[mi][2], aF[mi][3],
                     pA + row * ROWB + colh * 2);
            }
#pragma unroll
            for (int pi = 0; pi < 4; ++pi) {
                const int row  = warp_n * 64 + pi * 16 + (q >> 1) * 8 + lr;
                const int colh = kc + (q & 1) * 8;
                uint32_t r0, r1, r2, r3;
                LDM4(r0, r1, r2, r3, pB + row * ROWB + colh * 2);
                bF[pi * 2 + 0][0] = r0;  bF[pi * 2 + 0][1] = r1;
                bF[pi * 2 + 1][0] = r2;  bF[pi * 2 + 1][1] = r3;
            }
#pragma unroll
            for (int mi = 0; mi < 4; ++mi)
#pragma unroll
                for (int ni = 0; ni < 8; ++ni)
                    MMA16816(acc[mi][ni], aF[mi], bF[ni]);
        }
        cur = (cur + 1) % STAGES;
    }

    // epilogue: bias add, store, fused column sum/sumsq
    const int er = lane >> 2;         // 0..7
    const int ec = (lane & 3) * 2;
#pragma unroll
    for (int ni = 0; ni < 8; ++ni) {
        const int n  = n0 + warp_n * 64 + ni * 8 + ec;
        const float b0 = bias[n], b1 = bias[n + 1];
        float s0 = 0.f, s1 = 0.f, q0 = 0.f, q1 = 0.f;
#pragma unroll
        for (int mi = 0; mi < 4; ++mi) {
            const int mrow = m0 + warp_m * 64 + mi * 16 + er;
            float v0 = acc[mi][ni][0] + b0;
            float v1 = acc[mi][ni][1] + b1;
            float v2 = acc[mi][ni][2] + b0;
            float v3 = acc[mi][ni][3] + b1;
            *reinterpret_cast<float2*>(&X[(size_t)mrow * NB + n]) =
                make_float2(v0, v1);
            *reinterpret_cast<float2*>(&X[(size_t)(mrow + 8) * NB + n]) =
                make_float2(v2, v3);
            s0 += v0 + v2;           s1 += v1 + v3;
            q0 += v0 * v0 + v2 * v2; q1 += v1 * v1 + v3 * v3;
        }
#pragma unroll
        for (int off = 4; off < 32; off <<= 1) {
            s0 += __shfl_xor_sync(0xFFFFFFFFu, s0, off);
            s1 += __shfl_xor_sync(0xFFFFFFFFu, s1, off);
            q0 += __shfl_xor_sync(0xFFFFFFFFu, q0, off);
            q1 += __shfl_xor_sync(0xFFFFFFFFu, q1, off);
        }
        if (er == 0) {
            atomicAdd(&g_sum[n],       s0);
            atomicAdd(&g_sum[n + 1],   s1);
            atomicAdd(&g_sumsq[n],     q0);
            atomicAdd(&g_sumsq[n + 1], q1);
        }
    }
}

// ---------------------------------------------------------------------------
// Kernel 4: batchnorm + ReLU, float4-vectorized, in place
// ---------------------------------------------------------------------------
__global__ __launch_bounds__(256) void apply_kernel(
    float* __restrict__ X,
    const float* __restrict__ gamma,
    const float* __restrict__ beta)
{
    const int i4 = blockIdx.x * 256 + threadIdx.x;   // float4 index
    const int c4 = i4 & (NB / 4 - 1);                // column group
    const float inv_n = 1.0f / (float)BATCH;

    float4 s  = reinterpret_cast<const float4*>(g_sum)[c4];
    float4 ss = reinterpret_cast<const float4*>(g_sumsq)[c4];
    float4 g  = reinterpret_cast<const float4*>(gamma)[c4];
    float4 be = reinterpret_cast<const float4*>(beta)[c4];
    float4 v  = reinterpret_cast<float4*>(X)[i4];

    float m, is;
    m = s.x * inv_n; is = rsqrtf(ss.x * inv_n - m * m + BN_EPS);
    v.x = fmaxf((v.x - m) * is * g.x + be.x, 0.0f);
    m = s.y * inv_n; is = rsqrtf(ss.y * inv_n - m * m + BN_EPS);
    v.y = fmaxf((v.y - m) * is * g.y + be.y, 0.0f);
    m = s.z * inv_n; is = rsqrtf(ss.z * inv_n - m * m + BN_EPS);
    v.z = fmaxf((v.z - m) * is * g.z + be.z, 0.0f);
    m = s.w * inv_n; is = rsqrtf(ss.w * inv_n - m * m + BN_EPS);
    v.w = fmaxf((v.w - m) * is * g.w + be.w, 0.0f);

    reinterpret_cast<float4*>(X)[i4] = v;
}

// ---------------------------------------------------------------------------
// launch
// ---------------------------------------------------------------------------
extern "C" void kernel_launch(void* const* d_in, const int* in_sizes, int n_in,
                              void* d_out, int out_size)
{
    const float* h_states = (const float*)d_in[0];
    const float* end_pos  = (const float*)d_in[2];
    const float* W        = (const float*)d_in[4];
    const float* b        = (const float*)d_in[5];
    const float* gamma    = (const float*)d_in[6];
    const float* beta     = (const float*)d_in[7];
    float* X = (float*)d_out;

    __half *Ap, *Btp;
    cudaGetSymbolAddress((void**)&Ap,  g_A);
    cudaGetSymbolAddress((void**)&Btp, g_Bt);

    cudaFuncSetAttribute(gemm_kernel,
                         cudaFuncAttributeMaxDynamicSharedMemorySize, GEMM_SMEM);

    pool_kernel<<<BATCH, 64>>>(h_states, end_pos);
    wsplit_kernel<<<dim3(NB / 32, KDIM / 32), dim3(32, 8)>>>(W);

    gemm_kernel<<<dim3(NB / BNv, BATCH / BM), 256, GEMM_SMEM>>>(Ap, Btp, b, X);

    apply_kernel<<<(BATCH * NB / 4) / 256, 256>>>(X, gamma, beta);
}

// round 12
// speedup vs baseline: 6.2360x; 1.0607x over previous
#include <cuda_runtime.h>
#include <cuda_fp16.h>
#include <cstdint>
#include <math.h>

// ---------------- problem constants ----------------
#define BATCH  4096
#define NPED   64
#define HD     64
#define G2     64
#define KDIM   4096
#define NB     1024
#define BN_EPS 1e-5f

// ---------------- GEMM tiling ----------------
#define BM 128
#define BNv 128
#define BK 32
#define NK (KDIM / BK)          // 128
#define STAGES 4
#define ROWB 80                 // padded row bytes (32 halves + 8 pad)
#define STAGE_BYTES (2 * 128 * ROWB)     // 20480
#define GEMM_SMEM (STAGES * STAGE_BYTES) // 81920 -> 2 CTAs/SM

// ---------------- device scratch ----------------
__device__ __half g_A [(size_t)BATCH * KDIM];   // pooled features, fp16
__device__ __half g_Bt[(size_t)NB * KDIM];      // W^T (K-major), fp16
__device__ float  g_sum[NB];
__device__ float  g_sumsq[NB];

// ---------------- helpers ----------------
__device__ __forceinline__ uint32_t h2u(__half2 h) {
    return *reinterpret_cast<uint32_t*>(&h);
}

__device__ __forceinline__ uint32_t smem_u32(const void* p) {
    uint32_t a;
    asm("{ .reg .u64 t; cvta.to.shared.u64 t, %1; cvt.u32.u64 %0, t; }"
        : "=r"(a) : "l"(p));
    return a;
}

__device__ __forceinline__ void cp16(uint32_t dst, const void* src) {
    asm volatile("cp.async.cg.shared.global [%0], [%1], 16;"
                 :: "r"(dst), "l"(src) : "memory");
}

#define CP_COMMIT() asm volatile("cp.async.commit_group;" ::: "memory")
#define CP_WAIT(n)  asm volatile("cp.async.wait_group %0;" :: "n"(n) : "memory")

#define LDM4(r0, r1, r2, r3, a)                                         \
    asm volatile("ldmatrix.sync.aligned.m8n8.x4.shared.b16 "            \
                 "{%0,%1,%2,%3}, [%4];"                                 \
                 : "=r"(r0), "=r"(r1), "=r"(r2), "=r"(r3) : "r"(a))

#define MMA16816(c, a, b)                                               \
    asm volatile("mma.sync.aligned.m16n8k16.row.col.f32.f16.f16.f32 "   \
                 "{%0,%1,%2,%3}, {%4,%5,%6,%7}, {%8,%9}, {%0,%1,%2,%3};"\
                 : "+f"((c)[0]), "+f"((c)[1]), "+f"((c)[2]), "+f"((c)[3])\
                 : "r"((a)[0]), "r"((a)[1]), "r"((a)[2]), "r"((a)[3]),  \
                   "r"((b)[0]), "r"((b)[1]))

// ---------------------------------------------------------------------------
// Kernel 1 (merged): blocks [0,4096) social pooling -> fp16 A rows (uint4
// stores) + zero BN accumulators; blocks [4096,5120) transpose W -> fp16 Bt.
// ---------------------------------------------------------------------------
__global__ __launch_bounds__(64) void prep_kernel(
    const float* __restrict__ h,
    const float* __restrict__ pos,
    const float* __restrict__ W)
{
    __shared__ float buf[4224];          // pool: sp[4096]+spos[128f]; transp: 64x65
    const int blk = blockIdx.x;
    const int t   = threadIdx.x;

    if (blk < BATCH) {
        // ---------------- pooling path ----------------
        float* sp = buf;
        float2* spos = reinterpret_cast<float2*>(buf + 4096);
        const int base = (blk / NPED) * NPED;

        if (blk < 16) {
            g_sum  [blk * 64 + t] = 0.0f;
            g_sumsq[blk * 64 + t] = 0.0f;
        }

        for (int k = t; k < G2 * HD; k += 64) sp[k] = 0.0f;
        spos[t] = reinterpret_cast<const float2*>(pos)[base + t];
        __syncthreads();

        const int local_i = blk - base;
        const float2 pi = spos[local_i];
        const float tlx = pi.x - 1.0f, tly = pi.y + 1.0f;
        const float brx = pi.x + 1.0f, bry = pi.y - 1.0f;

        for (int j = 0; j < NPED; ++j) {
            if (j == local_i) continue;
            const float2 pj = spos[j];
            if (pj.x >= brx || pj.x <= tlx || pj.y >= tly || pj.y <= bry) continue;
            int cx = (int)floorf((pj.x - tlx) / 2.0f * 8.0f);
            int cy = (int)floorf((tly - pj.y) / 2.0f * 8.0f);
            int cell = min(max(cx + cy * 8, 0), G2 - 1);
            sp[cell * HD + t] += h[(size_t)(base + j) * HD + t];
        }
        __syncthreads();

        // vectorized fp16 output: 512 uint4 per row, 8 per thread
        uint4* dst = reinterpret_cast<uint4*>(g_A + (size_t)blk * KDIM);
#pragma unroll
        for (int i = 0; i < 8; ++i) {
            const int c = t + i * 64;            // uint4 index
            const float4 a = *reinterpret_cast<const float4*>(&sp[c * 8]);
            const float4 b = *reinterpret_cast<const float4*>(&sp[c * 8 + 4]);
            uint4 o;
            o.x = h2u(__floats2half2_rn(a.x, a.y));
            o.y = h2u(__floats2half2_rn(a.z, a.w));
            o.z = h2u(__floats2half2_rn(b.x, b.y));
            o.w = h2u(__floats2half2_rn(b.z, b.w));
            dst[c] = o;
        }
    } else {
        // ---------------- W transpose path ----------------
        const int idx = blk - BATCH;             // 0..1023
        const int k0  = (idx >> 4) * 64;         // 64 k-tiles
        const int n0  = (idx & 15) * 64;         // 16 n-tiles

#pragma unroll 8
        for (int kk = 0; kk < 64; ++kk)
            buf[kk * 65 + t] = W[(size_t)(k0 + kk) * NB + n0 + t];
        __syncthreads();

        // thread t writes row n0+t of Bt: 64 halves along k as 8 uint4
        uint4* dst = reinterpret_cast<uint4*>(g_Bt + (size_t)(n0 + t) * KDIM + k0);
#pragma unroll
        for (int c8 = 0; c8 < 8; ++c8) {
            const float* col = &buf[(c8 * 8) * 65 + t];
            uint4 o;
            o.x = h2u(__floats2half2_rn(col[0],      col[65]));
            o.y = h2u(__floats2half2_rn(col[2 * 65], col[3 * 65]));
            o.z = h2u(__floats2half2_rn(col[4 * 65], col[5 * 65]));
            o.w = h2u(__floats2half2_rn(col[6 * 65], col[7 * 65]));
            dst[c8] = o;
        }
    }
}

// ---------------------------------------------------------------------------
// Kernel 2: fp16 mma.sync GEMM  X = A * W + b, fused BN column stats
// CTA 128x128, BK=32, 4-stage cp.async, 2 CTAs/SM (256 CTAs in one wave).
// Warps 2(M) x 4(N); warp tile 64x32. One __syncthreads per K-iteration.
// ---------------------------------------------------------------------------
__global__ __launch_bounds__(256, 2) void gemm_kernel(
    const __half* __restrict__ A,   // [BATCH, KDIM]
    const __half* __restrict__ Bt,  // [NB, KDIM]
    const float* __restrict__ bias,
    float* __restrict__ X)          // [BATCH, NB]
{
    extern __shared__ __align__(16) char dsm[];
    const uint32_t sbase = smem_u32(dsm);
    const int t    = threadIdx.x;
    const int warp = t >> 5, lane = t & 31;
    const int m0 = blockIdx.y * BM;
    const int n0 = blockIdx.x * BNv;
    const int warp_m = warp & 1;     // 64-row slab
    const int warp_n = warp >> 1;    // 32-col slab

    float acc[4][4][4];
#pragma unroll
    for (int i = 0; i < 4; ++i)
#pragma unroll
        for (int j = 0; j < 4; ++j)
#pragma unroll
            for (int e = 0; e < 4; ++e) acc[i][j][e] = 0.0f;

    // loader: A and B tiles 128 rows x 4 chunks(16B) = 512 chunks each, 2/thread
    auto load_stage = [&](int s, int kt) {
        const int kk = kt * BK;
        const uint32_t sA = sbase + (uint32_t)s * STAGE_BYTES;
        const uint32_t sB = sA + 128 * ROWB;
#pragma unroll
        for (int i = 0; i < 2; ++i) {
            const int id = t + i * 256;
            const int r = id >> 2, c = (id & 3) * 8;
            cp16(sA + r * ROWB + c * 2, A  + (size_t)(m0 + r) * KDIM + kk + c);
            cp16(sB + r * ROWB + c * 2, Bt + (size_t)(n0 + r) * KDIM + kk + c);
        }
    };

#pragma unroll
    for (int s = 0; s < STAGES - 1; ++s) {
        load_stage(s, s);
        CP_COMMIT();
    }

    const int q  = lane >> 3;   // 0..3
    const int lr = lane & 7;

    for (int kt = 0; kt < NK; ++kt) {
        CP_WAIT(2);             // stage kt resident
        __syncthreads();        // everyone done with stage kt-1 (to be overwritten)

        if (kt + STAGES - 1 < NK)
            load_stage((kt + STAGES - 1) % STAGES, kt + STAGES - 1);
        CP_COMMIT();

        const uint32_t sA = sbase + (uint32_t)(kt % STAGES) * STAGE_BYTES;
        const uint32_t sB = sA + 128 * ROWB;

#pragma unroll
        for (int ks = 0; ks < 2; ++ks) {
            uint32_t aF[4][4];
            uint32_t bF[4][2];
#pragma unroll
            for (int mi = 0; mi < 4; ++mi) {
                const int row  = warp_m * 64 + mi * 16 + (q & 1) * 8 + lr;
                const int colh = ks * 16 + (q >> 1) * 8;
                LDM4(aF[mi][0], aF[mi][1], aF[mi][2], aF[mi][3],
                     sA + row * ROWB + colh * 2);
            }
#pragma unroll
            for (int pi = 0; pi < 2; ++pi) {
                const int row  = warp_n * 32 + pi * 16 + (q >> 1) * 8 + lr;
                const int colh = ks * 16 + (q & 1) * 8;
                uint32_t r0, r1, r2, r3;
                LDM4(r0, r1, r2, r3, sB + row * ROWB + colh * 2);
                bF[pi * 2 + 0][0] = r0;  bF[pi * 2 + 0][1] = r1;
                bF[pi * 2 + 1][0] = r2;  bF[pi * 2 + 1][1] = r3;
            }
#pragma unroll
            for (int mi = 0; mi < 4; ++mi)
#pragma unroll
                for (int ni = 0; ni < 4; ++ni)
                    MMA16816(acc[mi][ni], aF[mi], bF[ni]);
        }
    }

    // epilogue: bias add, store, fused column sum/sumsq (64 rows per warp)
    const int er = lane >> 2;         // 0..7
    const int ec = (lane & 3) * 2;
#pragma unroll
    for (int ni = 0; ni < 4; ++ni) {
        const int n  = n0 + warp_n * 32 + ni * 8 + ec;
        const float b0 = bias[n], b1 = bias[n + 1];
        float s0 = 0.f, s1 = 0.f, q0 = 0.f, q1 = 0.f;
#pragma unroll
        for (int mi = 0; mi < 4; ++mi) {
            const int mrow = m0 + warp_m * 64 + mi * 16 + er;
            float v0 = acc[mi][ni][0] + b0;
            float v1 = acc[mi][ni][1] + b1;
            float v2 = acc[mi][ni][2] + b0;
            float v3 = acc[mi][ni][3] + b1;
            *reinterpret_cast<float2*>(&X[(size_t)mrow * NB + n]) =
                make_float2(v0, v1);
            *reinterpret_cast<float2*>(&X[(size_t)(mrow + 8) * NB + n]) =
                make_float2(v2, v3);
            s0 += v0 + v2;           s1 += v1 + v3;
            q0 += v0 * v0 + v2 * v2; q1 += v1 * v1 + v3 * v3;
        }
#pragma unroll
        for (int off = 4; off < 32; off <<= 1) {
            s0 += __shfl_xor_sync(0xFFFFFFFFu, s0, off);
            s1 += __shfl_xor_sync(0xFFFFFFFFu, s1, off);
            q0 += __shfl_xor_sync(0xFFFFFFFFu, q0, off);
            q1 += __shfl_xor_sync(0xFFFFFFFFu, q1, off);
        }
        if (er == 0) {
            atomicAdd(&g_sum[n],       s0);
            atomicAdd(&g_sum[n + 1],   s1);
            atomicAdd(&g_sumsq[n],     q0);
            atomicAdd(&g_sumsq[n + 1], q1);
        }
    }
}

// ---------------------------------------------------------------------------
// Kernel 3: batchnorm + ReLU, float4-vectorized, in place
// ---------------------------------------------------------------------------
__global__ __launch_bounds__(256) void apply_kernel(
    float* __restrict__ X,
    const float* __restrict__ gamma,
    const float* __restrict__ beta)
{
    const int i4 = blockIdx.x * 256 + threadIdx.x;   // float4 index
    const int c4 = i4 & (NB / 4 - 1);                // column group
    const float inv_n = 1.0f / (float)BATCH;

    float4 s  = reinterpret_cast<const float4*>(g_sum)[c4];
    float4 ss = reinterpret_cast<const float4*>(g_sumsq)[c4];
    float4 g  = reinterpret_cast<const float4*>(gamma)[c4];
    float4 be = reinterpret_cast<const float4*>(beta)[c4];
    float4 v  = reinterpret_cast<float4*>(X)[i4];

    float m, is;
    m = s.x * inv_n; is = rsqrtf(ss.x * inv_n - m * m + BN_EPS);
    v.x = fmaxf((v.x - m) * is * g.x + be.x, 0.0f);
    m = s.y * inv_n; is = rsqrtf(ss.y * inv_n - m * m + BN_EPS);
    v.y = fmaxf((v.y - m) * is * g.y + be.y, 0.0f);
    m = s.z * inv_n; is = rsqrtf(ss.z * inv_n - m * m + BN_EPS);
    v.z = fmaxf((v.z - m) * is * g.z + be.z, 0.0f);
    m = s.w * inv_n; is = rsqrtf(ss.w * inv_n - m * m + BN_EPS);
    v.w = fmaxf((v.w - m) * is * g.w + be.w, 0.0f);

    reinterpret_cast<float4*>(X)[i4] = v;
}

// ---------------------------------------------------------------------------
// launch
// ---------------------------------------------------------------------------
extern "C" void kernel_launch(void* const* d_in, const int* in_sizes, int n_in,
                              void* d_out, int out_size)
{
    const float* h_states = (const float*)d_in[0];
    const float* end_pos  = (const float*)d_in[2];
    const float* W        = (const float*)d_in[4];
    const float* b        = (const float*)d_in[5];
    const float* gamma    = (const float*)d_in[6];
    const float* beta     = (const float*)d_in[7];
    float* X = (float*)d_out;

    __half *Ap, *Btp;
    cudaGetSymbolAddress((void**)&Ap,  g_A);
    cudaGetSymbolAddress((void**)&Btp, g_Bt);

    cudaFuncSetAttribute(gemm_kernel,
                         cudaFuncAttributeMaxDynamicSharedMemorySize, GEMM_SMEM);

    prep_kernel<<<BATCH + 1024, 64>>>(h_states, end_pos, W);

    gemm_kernel<<<dim3(NB / BNv, BATCH / BM), 256, GEMM_SMEM>>>(Ap, Btp, b, X);

    apply_kernel<<<(BATCH * NB / 4) / 256, 256>>>(X, gamma, beta);
}